// round 10
// baseline (speedup 1.0000x reference)
#include <cuda_runtime.h>
#include <cuda_bf16.h>
#include <math.h>
#include <stdint.h>

#define NN 100000
#define EE 250000
#define GG 4000
#define DD 300
#define D4 75        // DD/4
#define D2 600
#define LL 5
#define EPS 1e-5f

// ---------------- scratch (device globals; no allocation) ----------------
__device__ float g_h[(size_t)NN * DD];
__device__ float g_aggr[(size_t)NN * DD];
__device__ float g_hid[(size_t)NN * D2];
__device__ float g_pool[(size_t)GG * DD];
__device__ float g_vn[(size_t)GG * DD];
__device__ float g_vnin[(size_t)GG * DD];
__device__ float g_vnt[(size_t)GG * DD];
__device__ float g_cnt[GG];
__device__ int   g_tc[(size_t)NN * 6];
__device__ int   g_dc[(size_t)NN * 3];
__device__ float g_w1r[(size_t)LL * DD * D2];
__device__ float g_w2r[(size_t)LL * D2 * DD];
__device__ float g_vw1r[(size_t)(LL - 1) * DD * DD];
__device__ float g_vw2r[(size_t)(LL - 1) * DD * DD];

__device__ __forceinline__ float tf32r(float x) {
    uint32_t o;
    asm("cvt.rna.tf32.f32 %0, %1;" : "=r"(o) : "f"(x));
    return __uint_as_float(o);
}
__device__ __forceinline__ uint32_t tf32u(float x) {
    uint32_t o;
    asm("cvt.rna.tf32.f32 %0, %1;" : "=r"(o) : "f"(x));
    return o;
}
__device__ __forceinline__ void red4(float4* p, float4 v) {
    asm volatile("red.global.add.v4.f32 [%0], {%1,%2,%3,%4};"
                 :: "l"(p), "f"(v.x), "f"(v.y), "f"(v.z), "f"(v.w) : "memory");
}
__device__ __forceinline__ void red2(float* p, float a, float b) {
    asm volatile("red.global.add.v2.f32 [%0], {%1,%2};"
                 :: "l"(p), "f"(a), "f"(b) : "memory");
}

// ---------------- small utility kernels ----------------
__global__ void k_zero(float* p, long n) {
    long i = (long)blockIdx.x * blockDim.x + threadIdx.x;
    if (i < n) p[i] = 0.f;
}
__global__ void k_zeroi(int* p, long n) {
    long i = (long)blockIdx.x * blockDim.x + threadIdx.x;
    if (i < n) p[i] = 0;
}
__global__ void k_round(const float* __restrict__ s, float* __restrict__ d, long n) {
    long i = (long)blockIdx.x * blockDim.x + threadIdx.x;
    if (i < n) d[i] = tf32r(s[i]);
}
__global__ void k_count(const int* __restrict__ batch, float* cnt, int n) {
    int i = blockIdx.x * blockDim.x + threadIdx.x;
    if (i < n) atomicAdd(&cnt[batch[i]], 1.f);
}

__global__ void k_edgehist(const int* __restrict__ dst, const int* __restrict__ et,
                           const int* __restrict__ ed, int* __restrict__ tc,
                           int* __restrict__ dc, int E) {
    int i = blockIdx.x * blockDim.x + threadIdx.x;
    if (i >= E) return;
    int t = dst[i];
    atomicAdd(&tc[(size_t)t * 6 + et[i]], 1);
    atomicAdd(&dc[(size_t)t * 3 + ed[i]], 1);
}

__global__ void k_init_h(const int* __restrict__ x_atom, const int* __restrict__ x_chir,
                         const float* __restrict__ emb1, const float* __restrict__ emb2,
                         const float* __restrict__ vn_emb, float* __restrict__ h, long total) {
    long idx = (long)blockIdx.x * blockDim.x + threadIdx.x;
    if (idx >= total) return;
    int i = (int)(idx / DD);
    int d = (int)(idx % DD);
    h[idx] = emb1[(size_t)x_atom[i] * DD + d] + emb2[(size_t)x_chir[i] * DD + d] + vn_emb[d];
}

__global__ void k_init_vn(const float* __restrict__ vn_emb, float* __restrict__ vn, long total) {
    long idx = (long)blockIdx.x * blockDim.x + threadIdx.x;
    if (idx >= total) return;
    vn[idx] = vn_emb[idx % DD];
}

// warp per node, float4: aggr = h + selfloop + sum_t tc[t]*e1[t] + sum_u dc[u]*e2[u]
__global__ void k_aggr_init(const float4* __restrict__ h4,
                            const float4* __restrict__ e1l4, const float4* __restrict__ e2l4,
                            const int* __restrict__ tc, const int* __restrict__ dc,
                            float4* __restrict__ aggr4, int n) {
    int node = blockIdx.x * (blockDim.x >> 5) + (threadIdx.x >> 5);
    if (node >= n) return;
    int lane = threadIdx.x & 31;
    float ct[6], cd[3];
    #pragma unroll
    for (int t = 0; t < 6; t++) ct[t] = (float)tc[(size_t)node * 6 + t];
    #pragma unroll
    for (int u = 0; u < 3; u++) cd[u] = (float)dc[(size_t)node * 3 + u];
    ct[4] += 1.f;
    cd[0] += 1.f;
    const float4* hs = h4 + (size_t)node * D4;
    float4* as = aggr4 + (size_t)node * D4;
    #pragma unroll
    for (int i = 0; i < 3; i++) {
        int d = lane + i * 32;
        if (d >= D4) break;
        float4 v = hs[d];
        #pragma unroll
        for (int t = 0; t < 6; t++) {
            float4 e = e1l4[t * D4 + d];
            v.x = fmaf(ct[t], e.x, v.x); v.y = fmaf(ct[t], e.y, v.y);
            v.z = fmaf(ct[t], e.z, v.z); v.w = fmaf(ct[t], e.w, v.w);
        }
        #pragma unroll
        for (int u = 0; u < 3; u++) {
            float4 e = e2l4[u * D4 + d];
            v.x = fmaf(cd[u], e.x, v.x); v.y = fmaf(cd[u], e.y, v.y);
            v.z = fmaf(cd[u], e.z, v.z); v.w = fmaf(cd[u], e.w, v.w);
        }
        as[d] = v;
    }
}

// warp per edge, vector red: aggr[dst] += h[src]
__global__ void k_scatter(const float4* __restrict__ h4,
                          const int* __restrict__ src, const int* __restrict__ dst,
                          float4* __restrict__ aggr4, int E) {
    int e = blockIdx.x * (blockDim.x >> 5) + (threadIdx.x >> 5);
    if (e >= E) return;
    int lane = threadIdx.x & 31;
    const float4* hs = h4 + (size_t)src[e] * D4;
    float4* at = aggr4 + (size_t)dst[e] * D4;
    #pragma unroll
    for (int i = 0; i < 3; i++) {
        int d = lane + i * 32;
        if (d < D4) red4(at + d, hs[d]);
    }
}

// warp per node, float4: h[i] += vn[batch[i]]
__global__ void k_addvn(float4* __restrict__ h4, const float4* __restrict__ vn4,
                        const int* __restrict__ batch, int n) {
    int node = blockIdx.x * (blockDim.x >> 5) + (threadIdx.x >> 5);
    if (node >= n) return;
    int lane = threadIdx.x & 31;
    const float4* vs = vn4 + (size_t)batch[node] * D4;
    float4* hs = h4 + (size_t)node * D4;
    #pragma unroll
    for (int i = 0; i < 3; i++) {
        int d = lane + i * 32;
        if (d < D4) {
            float4 a = hs[d], b = vs[d];
            a.x += b.x; a.y += b.y; a.z += b.z; a.w += b.w;
            hs[d] = a;
        }
    }
}

// vn_in = pooled/cnt + vn
__global__ void k_vnprep(const float* __restrict__ pooled, const float* __restrict__ cnt,
                         const float* __restrict__ vn, float* __restrict__ out, long total) {
    long idx = (long)blockIdx.x * blockDim.x + threadIdx.x;
    if (idx >= total) return;
    int g = (int)(idx / DD);
    out[idx] = pooled[idx] / fmaxf(cnt[g], 1.f) + vn[idx];
}

// LayerNorm + ReLU over rows of [GG x DD], in place. block=128, grid=GG
__global__ void k_ln(float* __restrict__ t, const float* __restrict__ g,
                     const float* __restrict__ b) {
    int gid = blockIdx.x;
    int tid = threadIdx.x;
    float* row = t + (size_t)gid * DD;
    float v[3];
    float s = 0.f;
    #pragma unroll
    for (int i = 0; i < 3; i++) {
        int d = tid + i * 128;
        v[i] = (d < DD) ? row[d] : 0.f;
        s += v[i];
    }
    __shared__ float red[4];
    __shared__ float redb[4];
    for (int o = 16; o; o >>= 1) s += __shfl_xor_sync(~0u, s, o);
    if ((tid & 31) == 0) red[tid >> 5] = s;
    __syncthreads();
    s = red[0] + red[1] + red[2] + red[3];
    float mu = s / DD;
    float q = 0.f;
    #pragma unroll
    for (int i = 0; i < 3; i++) {
        int d = tid + i * 128;
        float dv = (d < DD) ? (v[i] - mu) : 0.f;
        q += dv * dv;
    }
    for (int o = 16; o; o >>= 1) q += __shfl_xor_sync(~0u, q, o);
    if ((tid & 31) == 0) redb[tid >> 5] = q;
    __syncthreads();
    q = redb[0] + redb[1] + redb[2] + redb[3];
    float rs = rsqrtf(q / DD + EPS);
    #pragma unroll
    for (int i = 0; i < 3; i++) {
        int d = tid + i * 128;
        if (d < DD) {
            float x = (v[i] - mu) * rs * g[d] + b[d];
            row[d] = fmaxf(x, 0.f);
        }
    }
}

// ---------------- TF32 tensor-core GEMM, 3-stage cp.async, single sync/iter ----------------
// 8 warps (4M x 2N), warp tile 32x64 — R6 compute geometry
// mode 0: ReLU(x+bias); 1: BN+ReLU + red.v2 into pool[batch]; 2: BN; 3: bias only

__device__ __forceinline__ void mma_tf32(float* c, const uint32_t* a, const uint32_t* b) {
    asm volatile(
        "mma.sync.aligned.m16n8k8.row.col.f32.tf32.tf32.f32 "
        "{%0,%1,%2,%3}, {%4,%5,%6,%7}, {%8,%9}, {%0,%1,%2,%3};\n"
        : "+f"(c[0]), "+f"(c[1]), "+f"(c[2]), "+f"(c[3])
        : "r"(a[0]), "r"(a[1]), "r"(a[2]), "r"(a[3]), "r"(b[0]), "r"(b[1]));
}

#define BM 128
#define BN 128
#define BK 32
#define AST 36
#define BST 136
#define ASZ (BM * AST)
#define BSZ (BK * BST)
#define NSTG 3
#define SMEM_GEMM (NSTG * (ASZ + BSZ) * 4)

extern __shared__ float smem_dyn[];

__device__ __forceinline__ void g_prefetch(const float* __restrict__ A,
                                           const float* __restrict__ B,
                                           float* As, float* Bs,
                                           int Nrows, int K, int M,
                                           int row0, int col0, int k0,
                                           int ra, int kq, int kb, int nq) {
    #pragma unroll
    for (int p = 0; p < 4; p++) {
        int rr = ra + p * 32;
        int gr = row0 + rr, gk = k0 + kq;
        bool ok = (gr < Nrows && gk < K);
        unsigned d = (unsigned)__cvta_generic_to_shared(&As[rr * AST + kq]);
        const float* s = ok ? (A + (size_t)gr * K + gk) : A;
        int sz = ok ? 16 : 0;
        asm volatile("cp.async.ca.shared.global [%0], [%1], 16, %2;\n" :: "r"(d), "l"(s), "r"(sz));
    }
    #pragma unroll
    for (int p = 0; p < 4; p++) {
        int kr = kb + p * 8;
        int gk = k0 + kr, gc = col0 + nq;
        bool ok = (gk < K && gc < M);
        unsigned d = (unsigned)__cvta_generic_to_shared(&Bs[kr * BST + nq]);
        const float* s = ok ? (B + (size_t)gk * M + gc) : B;
        int sz = ok ? 16 : 0;
        asm volatile("cp.async.ca.shared.global [%0], [%1], 16, %2;\n" :: "r"(d), "l"(s), "r"(sz));
    }
}

__global__ __launch_bounds__(256) void k_gemm_tf32(const float* __restrict__ A,
                                                   const float* __restrict__ B,
                                                   float* __restrict__ C,
                                                   int Nrows, int K, int M,
                                                   const float* __restrict__ bias,
                                                   const float* __restrict__ bng,
                                                   const float* __restrict__ bnb,
                                                   const float* __restrict__ bnm,
                                                   const float* __restrict__ bnv,
                                                   float* __restrict__ pool,
                                                   const int* __restrict__ batch,
                                                   int mode) {
    float* As = smem_dyn;                       // [NSTG][ASZ]
    float* Bs = smem_dyn + NSTG * ASZ;          // [NSTG][BSZ]

    int tid = threadIdx.x;
    int warp = tid >> 5, lane = tid & 31;
    int warp_m = warp & 3;
    int warp_n = warp >> 2;
    int row0 = blockIdx.y * BM;
    int col0 = blockIdx.x * BN;
    int lq = lane >> 2, lr = lane & 3;

    float acc[2][8][4] = {};

    int ra = tid >> 3;
    int kq = (tid & 7) * 4;
    int kb = tid >> 5;
    int nq = (tid & 31) * 4;
    int nT = (K + BK - 1) / BK;

    // prologue: tiles 0 and 1
    g_prefetch(A, B, As, Bs, Nrows, K, M, row0, col0, 0, ra, kq, kb, nq);
    asm volatile("cp.async.commit_group;\n");
    if (nT > 1)
        g_prefetch(A, B, As + ASZ, Bs + BSZ, Nrows, K, M, row0, col0, BK, ra, kq, kb, nq);
    asm volatile("cp.async.commit_group;\n");

    for (int t = 0; t < nT; t++) {
        asm volatile("cp.async.wait_group 1;\n");   // tile t resident
        __syncthreads();                            // all warps done with iter t-1 (incl. buffer (t+2)%3 reads)
        if (t + 2 < nT) {
            int buf = (t + 2) % NSTG;
            g_prefetch(A, B, As + buf * ASZ, Bs + buf * BSZ, Nrows, K, M,
                       row0, col0, (t + 2) * BK, ra, kq, kb, nq);
        }
        asm volatile("cp.async.commit_group;\n");   // unconditional: keep group accounting uniform

        const float* Asb = As + (t % NSTG) * ASZ;
        const float* Bsb = Bs + (t % NSTG) * BSZ;
        #pragma unroll
        for (int ks = 0; ks < 4; ks++) {
            int k8 = ks * 8;
            uint32_t af[2][4], bf[8][2];
            int ar = warp_m * 32 + lq;
            int ac = k8 + lr;
            #pragma unroll
            for (int mt = 0; mt < 2; mt++) {
                const float* base = Asb + (ar + mt * 16) * AST + ac;
                af[mt][0] = tf32u(base[0]);
                af[mt][1] = tf32u(base[8 * AST]);
                af[mt][2] = tf32u(base[4]);
                af[mt][3] = tf32u(base[8 * AST + 4]);
            }
            int bc = warp_n * 64 + lq;
            #pragma unroll
            for (int nt = 0; nt < 8; nt++) {
                const float* base = Bsb + (k8 + lr) * BST + bc + nt * 8;
                bf[nt][0] = __float_as_uint(base[0]);
                bf[nt][1] = __float_as_uint(base[4 * BST]);
            }
            #pragma unroll
            for (int mt = 0; mt < 2; mt++)
                #pragma unroll
                for (int nt = 0; nt < 8; nt++)
                    mma_tf32(acc[mt][nt], af[mt], bf[nt]);
        }
        // no trailing sync: next iteration's top barrier protects buffer reuse
    }

    // --- epilogue: pairwise (float2) stores, vector pool reduction ---
    #pragma unroll
    for (int mt = 0; mt < 2; mt++) {
        #pragma unroll
        for (int half = 0; half < 2; half++) {
            int row = row0 + warp_m * 32 + mt * 16 + lq + half * 8;
            if (row >= Nrows) continue;
            int bg = (mode == 1) ? batch[row] : 0;
            #pragma unroll
            for (int nt = 0; nt < 8; nt++) {
                int col = col0 + warp_n * 64 + nt * 8 + lr * 2;
                if (col >= M) continue;
                float v0 = acc[mt][nt][half * 2 + 0] + bias[col];
                float v1 = acc[mt][nt][half * 2 + 1] + bias[col + 1];
                if (mode == 0) {
                    v0 = fmaxf(v0, 0.f); v1 = fmaxf(v1, 0.f);
                } else if (mode != 3) {
                    float sc0 = bng[col] * rsqrtf(bnv[col] + EPS);
                    float sc1 = bng[col + 1] * rsqrtf(bnv[col + 1] + EPS);
                    v0 = (v0 - bnm[col]) * sc0 + bnb[col];
                    v1 = (v1 - bnm[col + 1]) * sc1 + bnb[col + 1];
                    if (mode == 1) { v0 = fmaxf(v0, 0.f); v1 = fmaxf(v1, 0.f); }
                }
                *(float2*)(C + (size_t)row * M + col) = make_float2(v0, v1);
                if (mode == 1) red2(pool + (size_t)bg * DD + col, v0, v1);
            }
        }
    }
}

// ---------------- launch ----------------
extern "C" void kernel_launch(void* const* d_in, const int* in_sizes, int n_in,
                              void* d_out, int out_size) {
    const int*   x_atom  = (const int*)d_in[0];
    const int*   x_chir  = (const int*)d_in[1];
    const int*   src     = (const int*)d_in[2];
    const int*   dst     = (const int*)d_in[3];
    const int*   etype   = (const int*)d_in[4];
    const int*   edir    = (const int*)d_in[5];
    const int*   batch   = (const int*)d_in[6];
    const float* x_emb1  = (const float*)d_in[7];
    const float* x_emb2  = (const float*)d_in[8];
    const float* edge_e1 = (const float*)d_in[9];
    const float* edge_e2 = (const float*)d_in[10];
    const float* mlp_w1  = (const float*)d_in[11];
    const float* mlp_b1  = (const float*)d_in[12];
    const float* mlp_w2  = (const float*)d_in[13];
    const float* mlp_b2  = (const float*)d_in[14];
    const float* bng     = (const float*)d_in[15];
    const float* bnb     = (const float*)d_in[16];
    const float* bnm     = (const float*)d_in[17];
    const float* bnv     = (const float*)d_in[18];
    const float* vn_emb  = (const float*)d_in[19];
    const float* vn_w1   = (const float*)d_in[20];
    const float* vn_b1   = (const float*)d_in[21];
    const float* vn_lng  = (const float*)d_in[22];
    const float* vn_lnb  = (const float*)d_in[23];
    const float* vn_w2   = (const float*)d_in[24];
    const float* vn_b2   = (const float*)d_in[25];
    float* out = (float*)d_out;

    float *p_h, *p_aggr, *p_hid, *p_pool, *p_vn, *p_vnin, *p_vnt, *p_cnt;
    float *p_w1r, *p_w2r, *p_vw1r, *p_vw2r;
    int *p_tc, *p_dc;
    cudaGetSymbolAddress((void**)&p_h, g_h);
    cudaGetSymbolAddress((void**)&p_aggr, g_aggr);
    cudaGetSymbolAddress((void**)&p_hid, g_hid);
    cudaGetSymbolAddress((void**)&p_pool, g_pool);
    cudaGetSymbolAddress((void**)&p_vn, g_vn);
    cudaGetSymbolAddress((void**)&p_vnin, g_vnin);
    cudaGetSymbolAddress((void**)&p_vnt, g_vnt);
    cudaGetSymbolAddress((void**)&p_cnt, g_cnt);
    cudaGetSymbolAddress((void**)&p_w1r, g_w1r);
    cudaGetSymbolAddress((void**)&p_w2r, g_w2r);
    cudaGetSymbolAddress((void**)&p_vw1r, g_vw1r);
    cudaGetSymbolAddress((void**)&p_vw2r, g_vw2r);
    cudaGetSymbolAddress((void**)&p_tc, g_tc);
    cudaGetSymbolAddress((void**)&p_dc, g_dc);

    cudaFuncSetAttribute(k_gemm_tf32, cudaFuncAttributeMaxDynamicSharedMemorySize, SMEM_GEMM);

    const long ND = (long)NN * DD;
    const long GD = (long)GG * DD;
    const int TPB = 256;
    dim3 bElem((unsigned)((ND + TPB - 1) / TPB));
    dim3 bGD((unsigned)((GD + TPB - 1) / TPB));

    {
        long n1 = (long)LL * DD * D2;
        long n2 = (long)LL * D2 * DD;
        long n3 = (long)(LL - 1) * DD * DD;
        k_round<<<(unsigned)((n1 + TPB - 1) / TPB), TPB>>>(mlp_w1, p_w1r, n1);
        k_round<<<(unsigned)((n2 + TPB - 1) / TPB), TPB>>>(mlp_w2, p_w2r, n2);
        k_round<<<(unsigned)((n3 + TPB - 1) / TPB), TPB>>>(vn_w1, p_vw1r, n3);
        k_round<<<(unsigned)((n3 + TPB - 1) / TPB), TPB>>>(vn_w2, p_vw2r, n3);
    }

    k_zero<<<(GG + TPB - 1) / TPB, TPB>>>(p_cnt, GG);
    k_count<<<(NN + TPB - 1) / TPB, TPB>>>(batch, p_cnt, NN);
    k_zeroi<<<(unsigned)(((long)NN * 6 + TPB - 1) / TPB), TPB>>>(p_tc, (long)NN * 6);
    k_zeroi<<<(unsigned)(((long)NN * 3 + TPB - 1) / TPB), TPB>>>(p_dc, (long)NN * 3);
    k_edgehist<<<(EE + TPB - 1) / TPB, TPB>>>(dst, etype, edir, p_tc, p_dc, EE);

    k_init_h<<<bElem, TPB>>>(x_atom, x_chir, x_emb1, x_emb2, vn_emb, p_h, ND);
    k_init_vn<<<bGD, TPB>>>(vn_emb, p_vn, GD);

    for (int l = 0; l < LL; l++) {
        const float4* e1l4 = (const float4*)(edge_e1 + (size_t)l * 6 * DD);
        const float4* e2l4 = (const float4*)(edge_e2 + (size_t)l * 3 * DD);

        k_aggr_init<<<(NN + 7) / 8, 256>>>((const float4*)p_h, e1l4, e2l4, p_tc, p_dc,
                                           (float4*)p_aggr, NN);
        k_scatter<<<(EE + 3) / 4, 128>>>((const float4*)p_h, src, dst, (float4*)p_aggr, EE);

        if (l < LL - 1) k_zero<<<bGD, TPB>>>(p_pool, GD);

        {
            dim3 grid((D2 + BN - 1) / BN, (NN + BM - 1) / BM);
            k_gemm_tf32<<<grid, 256, SMEM_GEMM>>>(p_aggr, p_w1r + (size_t)l * DD * D2, p_hid,
                                       NN, DD, D2, mlp_b1 + (size_t)l * D2,
                                       nullptr, nullptr, nullptr, nullptr, nullptr, nullptr, 0);
        }
        {
            float* zdst = (l == LL - 1) ? out : p_h;
            int mode = (l == LL - 1) ? 2 : 1;
            dim3 grid((DD + BN - 1) / BN, (NN + BM - 1) / BM);
            k_gemm_tf32<<<grid, 256, SMEM_GEMM>>>(p_hid, p_w2r + (size_t)l * D2 * DD, zdst,
                                       NN, D2, DD, mlp_b2 + (size_t)l * DD,
                                       bng + (size_t)l * DD, bnb + (size_t)l * DD,
                                       bnm + (size_t)l * DD, bnv + (size_t)l * DD,
                                       p_pool, batch, mode);
        }

        if (l < LL - 1) {
            k_vnprep<<<bGD, TPB>>>(p_pool, p_cnt, p_vn, p_vnin, GD);
            {
                dim3 grid((DD + BN - 1) / BN, (GG + BM - 1) / BM);
                k_gemm_tf32<<<grid, 256, SMEM_GEMM>>>(p_vnin, p_vw1r + (size_t)l * DD * DD, p_vnt,
                                           GG, DD, DD, vn_b1 + (size_t)l * DD,
                                           nullptr, nullptr, nullptr, nullptr, nullptr, nullptr, 3);
            }
            k_ln<<<GG, 128>>>(p_vnt, vn_lng + (size_t)l * DD, vn_lnb + (size_t)l * DD);
            {
                dim3 grid((DD + BN - 1) / BN, (GG + BM - 1) / BM);
                k_gemm_tf32<<<grid, 256, SMEM_GEMM>>>(p_vnt, p_vw2r + (size_t)l * DD * DD, p_vn,
                                           GG, DD, DD, vn_b2 + (size_t)l * DD,
                                           nullptr, nullptr, nullptr, nullptr, nullptr, nullptr, 3);
            }
            k_addvn<<<(NN + 7) / 8, 256>>>((float4*)p_h, (const float4*)p_vn, batch, NN);
        }
    }
}

// round 11
// speedup vs baseline: 1.3559x; 1.3559x over previous
#include <cuda_runtime.h>
#include <cuda_bf16.h>
#include <math.h>
#include <stdint.h>

#define NN 100000
#define EE 250000
#define GG 4000
#define DD 300
#define D4 75        // DD/4
#define D2 600
#define LL 5
#define EPS 1e-5f

// ---------------- scratch (device globals; no allocation) ----------------
// g_h holds z (pre-virtual-node). vn contribution is added at consumption
// points (k_aggr_init / k_scatter) as vn[batch[.]].
__device__ float g_h[(size_t)NN * DD];
__device__ float g_aggr[(size_t)NN * DD];
__device__ float g_hid[(size_t)NN * D2];
__device__ float g_pool[(size_t)GG * DD];
__device__ float g_vn[(size_t)GG * DD];
__device__ float g_vnin[(size_t)GG * DD];
__device__ float g_vnt[(size_t)GG * DD];
__device__ float g_cnt[GG];
__device__ int   g_tc[(size_t)NN * 6];
__device__ int   g_dc[(size_t)NN * 3];
__device__ float g_w1r[(size_t)LL * DD * D2];
__device__ float g_w2r[(size_t)LL * D2 * DD];
__device__ float g_vw1r[(size_t)(LL - 1) * DD * DD];
__device__ float g_vw2r[(size_t)(LL - 1) * DD * DD];

__device__ __forceinline__ float tf32r(float x) {
    uint32_t o;
    asm("cvt.rna.tf32.f32 %0, %1;" : "=r"(o) : "f"(x));
    return __uint_as_float(o);
}
__device__ __forceinline__ uint32_t tf32u(float x) {
    uint32_t o;
    asm("cvt.rna.tf32.f32 %0, %1;" : "=r"(o) : "f"(x));
    return o;
}
__device__ __forceinline__ void red4(float4* p, float4 v) {
    asm volatile("red.global.add.v4.f32 [%0], {%1,%2,%3,%4};"
                 :: "l"(p), "f"(v.x), "f"(v.y), "f"(v.z), "f"(v.w) : "memory");
}
__device__ __forceinline__ void red2(float* p, float a, float b) {
    asm volatile("red.global.add.v2.f32 [%0], {%1,%2};"
                 :: "l"(p), "f"(a), "f"(b) : "memory");
}

// ---------------- small utility kernels ----------------
__global__ void k_zero(float* p, long n) {
    long i = (long)blockIdx.x * blockDim.x + threadIdx.x;
    if (i < n) p[i] = 0.f;
}
__global__ void k_zeroi(int* p, long n) {
    long i = (long)blockIdx.x * blockDim.x + threadIdx.x;
    if (i < n) p[i] = 0;
}
__global__ void k_round(const float* __restrict__ s, float* __restrict__ d, long n) {
    long i = (long)blockIdx.x * blockDim.x + threadIdx.x;
    if (i < n) d[i] = tf32r(s[i]);
}
__global__ void k_count(const int* __restrict__ batch, float* cnt, int n) {
    int i = blockIdx.x * blockDim.x + threadIdx.x;
    if (i < n) atomicAdd(&cnt[batch[i]], 1.f);
}

__global__ void k_edgehist(const int* __restrict__ dst, const int* __restrict__ et,
                           const int* __restrict__ ed, int* __restrict__ tc,
                           int* __restrict__ dc, int E) {
    int i = blockIdx.x * blockDim.x + threadIdx.x;
    if (i >= E) return;
    int t = dst[i];
    atomicAdd(&tc[(size_t)t * 6 + et[i]], 1);
    atomicAdd(&dc[(size_t)t * 3 + ed[i]], 1);
}

// h = emb1[x_atom] + emb2[x_chir]   (NO vn term — applied at consumption)
__global__ void k_init_h(const int* __restrict__ x_atom, const int* __restrict__ x_chir,
                         const float* __restrict__ emb1, const float* __restrict__ emb2,
                         float* __restrict__ h, long total) {
    long idx = (long)blockIdx.x * blockDim.x + threadIdx.x;
    if (idx >= total) return;
    int i = (int)(idx / DD);
    int d = (int)(idx % DD);
    h[idx] = emb1[(size_t)x_atom[i] * DD + d] + emb2[(size_t)x_chir[i] * DD + d];
}

__global__ void k_init_vn(const float* __restrict__ vn_emb, float* __restrict__ vn, long total) {
    long idx = (long)blockIdx.x * blockDim.x + threadIdx.x;
    if (idx >= total) return;
    vn[idx] = vn_emb[idx % DD];
}

// warp per node, float4:
// aggr = (h+vn[bg]) + selfloop + sum_t tc[t]*e1[t] + sum_u dc[u]*e2[u]
// note: incoming messages each carry their own vn[bg] (same graph), handled by
// counting: total vn contribution = (1 + deg) * vn[bg]; deg = sum_t tc[t].
__global__ void k_aggr_init(const float4* __restrict__ h4,
                            const float4* __restrict__ vn4,
                            const int* __restrict__ batch,
                            const float4* __restrict__ e1l4, const float4* __restrict__ e2l4,
                            const int* __restrict__ tc, const int* __restrict__ dc,
                            float4* __restrict__ aggr4, int n) {
    int node = blockIdx.x * (blockDim.x >> 5) + (threadIdx.x >> 5);
    if (node >= n) return;
    int lane = threadIdx.x & 31;
    float ct[6], cd[3];
    #pragma unroll
    for (int t = 0; t < 6; t++) ct[t] = (float)tc[(size_t)node * 6 + t];
    #pragma unroll
    for (int u = 0; u < 3; u++) cd[u] = (float)dc[(size_t)node * 3 + u];
    ct[4] += 1.f;  // self loop type 4
    cd[0] += 1.f;  // self loop dir 0
    const float4* hs = h4 + (size_t)node * D4;
    const float4* vs = vn4 + (size_t)batch[node] * D4;
    float4* as = aggr4 + (size_t)node * D4;
    #pragma unroll
    for (int i = 0; i < 3; i++) {
        int d = lane + i * 32;
        if (d >= D4) break;
        float4 v = hs[d];
        float4 w = vs[d];
        v.x += w.x; v.y += w.y; v.z += w.z; v.w += w.w;   // self term's vn
        #pragma unroll
        for (int t = 0; t < 6; t++) {
            float4 e = e1l4[t * D4 + d];
            v.x = fmaf(ct[t], e.x, v.x); v.y = fmaf(ct[t], e.y, v.y);
            v.z = fmaf(ct[t], e.z, v.z); v.w = fmaf(ct[t], e.w, v.w);
        }
        #pragma unroll
        for (int u = 0; u < 3; u++) {
            float4 e = e2l4[u * D4 + d];
            v.x = fmaf(cd[u], e.x, v.x); v.y = fmaf(cd[u], e.y, v.y);
            v.z = fmaf(cd[u], e.z, v.z); v.w = fmaf(cd[u], e.w, v.w);
        }
        as[d] = v;
    }
}

// warp per edge, vector red: aggr[dst] += h[src] + vn[batch[src]]
__global__ void k_scatter(const float4* __restrict__ h4,
                          const float4* __restrict__ vn4,
                          const int* __restrict__ batch,
                          const int* __restrict__ src, const int* __restrict__ dst,
                          float4* __restrict__ aggr4, int E) {
    int e = blockIdx.x * (blockDim.x >> 5) + (threadIdx.x >> 5);
    if (e >= E) return;
    int lane = threadIdx.x & 31;
    int s = src[e];
    const float4* hs = h4 + (size_t)s * D4;
    const float4* vs = vn4 + (size_t)batch[s] * D4;
    float4* at = aggr4 + (size_t)dst[e] * D4;
    #pragma unroll
    for (int i = 0; i < 3; i++) {
        int d = lane + i * 32;
        if (d < D4) {
            float4 a = hs[d], b = vs[d];
            a.x += b.x; a.y += b.y; a.z += b.z; a.w += b.w;
            red4(at + d, a);
        }
    }
}

// vn_in = pooled/cnt + vn
__global__ void k_vnprep(const float* __restrict__ pooled, const float* __restrict__ cnt,
                         const float* __restrict__ vn, float* __restrict__ out, long total) {
    long idx = (long)blockIdx.x * blockDim.x + threadIdx.x;
    if (idx >= total) return;
    int g = (int)(idx / DD);
    out[idx] = pooled[idx] / fmaxf(cnt[g], 1.f) + vn[idx];
}

// LayerNorm + ReLU over rows of [GG x DD], in place. block=128, grid=GG
__global__ void k_ln(float* __restrict__ t, const float* __restrict__ g,
                     const float* __restrict__ b) {
    int gid = blockIdx.x;
    int tid = threadIdx.x;
    float* row = t + (size_t)gid * DD;
    float v[3];
    float s = 0.f;
    #pragma unroll
    for (int i = 0; i < 3; i++) {
        int d = tid + i * 128;
        v[i] = (d < DD) ? row[d] : 0.f;
        s += v[i];
    }
    __shared__ float red[4];
    __shared__ float redb[4];
    for (int o = 16; o; o >>= 1) s += __shfl_xor_sync(~0u, s, o);
    if ((tid & 31) == 0) red[tid >> 5] = s;
    __syncthreads();
    s = red[0] + red[1] + red[2] + red[3];
    float mu = s / DD;
    float q = 0.f;
    #pragma unroll
    for (int i = 0; i < 3; i++) {
        int d = tid + i * 128;
        float dv = (d < DD) ? (v[i] - mu) : 0.f;
        q += dv * dv;
    }
    for (int o = 16; o; o >>= 1) q += __shfl_xor_sync(~0u, q, o);
    if ((tid & 31) == 0) redb[tid >> 5] = q;
    __syncthreads();
    q = redb[0] + redb[1] + redb[2] + redb[3];
    float rs = rsqrtf(q / DD + EPS);
    #pragma unroll
    for (int i = 0; i < 3; i++) {
        int d = tid + i * 128;
        if (d < DD) {
            float x = (v[i] - mu) * rs * g[d] + b[d];
            row[d] = fmaxf(x, 0.f);
        }
    }
}

// ---------------- TF32 tensor-core GEMM, 2-stage cp.async (R8 config, frozen) ----------------
// mode 0: ReLU(x+bias); 1: BN+ReLU + red.v2 into pool[batch]; 2: BN; 3: bias only
// mode 4: like 2 but also writes out to separate buffer? (not used)

__device__ __forceinline__ void mma_tf32(float* c, const uint32_t* a, const uint32_t* b) {
    asm volatile(
        "mma.sync.aligned.m16n8k8.row.col.f32.tf32.tf32.f32 "
        "{%0,%1,%2,%3}, {%4,%5,%6,%7}, {%8,%9}, {%0,%1,%2,%3};\n"
        : "+f"(c[0]), "+f"(c[1]), "+f"(c[2]), "+f"(c[3])
        : "r"(a[0]), "r"(a[1]), "r"(a[2]), "r"(a[3]), "r"(b[0]), "r"(b[1]));
}

#define BM 128
#define BN 128
#define BK 32
#define AST 36
#define BST 136
#define ASZ (BM * AST)
#define BSZ (BK * BST)
#define SMEM_GEMM (2 * (ASZ + BSZ) * 4)

extern __shared__ float smem_dyn[];

__global__ __launch_bounds__(256, 2) void k_gemm_tf32(const float* __restrict__ A,
                                                      const float* __restrict__ B,
                                                      float* __restrict__ C,
                                                      int Nrows, int K, int M,
                                                      const float* __restrict__ bias,
                                                      const float* __restrict__ bng,
                                                      const float* __restrict__ bnb,
                                                      const float* __restrict__ bnm,
                                                      const float* __restrict__ bnv,
                                                      float* __restrict__ pool,
                                                      const int* __restrict__ batch,
                                                      int mode) {
    float* As = smem_dyn;                      // [2][ASZ]
    float* Bs = smem_dyn + 2 * ASZ;            // [2][BSZ]

    int tid = threadIdx.x;
    int warp = tid >> 5, lane = tid & 31;
    int warp_m = warp & 3;
    int warp_n = warp >> 2;
    int row0 = blockIdx.y * BM;
    int col0 = blockIdx.x * BN;
    int lq = lane >> 2, lr = lane & 3;

    float acc[2][8][4] = {};

    int ra = tid >> 3;
    int kq = (tid & 7) * 4;
    int kb = tid >> 5;
    int nq = (tid & 31) * 4;
    int nT = (K + BK - 1) / BK;

    {
        #pragma unroll
        for (int p = 0; p < 4; p++) {
            int rr = ra + p * 32;
            int gr = row0 + rr, gk = kq;
            bool ok = (gr < Nrows && gk < K);
            unsigned d = (unsigned)__cvta_generic_to_shared(&As[rr * AST + kq]);
            const float* s = ok ? (A + (size_t)gr * K + gk) : A;
            int sz = ok ? 16 : 0;
            asm volatile("cp.async.ca.shared.global [%0], [%1], 16, %2;\n" :: "r"(d), "l"(s), "r"(sz));
        }
        #pragma unroll
        for (int p = 0; p < 4; p++) {
            int kr = kb + p * 8;
            int gk = kr, gc = col0 + nq;
            bool ok = (gk < K && gc < M);
            unsigned d = (unsigned)__cvta_generic_to_shared(&Bs[kr * BST + nq]);
            const float* s = ok ? (B + (size_t)gk * M + gc) : B;
            int sz = ok ? 16 : 0;
            asm volatile("cp.async.ca.shared.global [%0], [%1], 16, %2;\n" :: "r"(d), "l"(s), "r"(sz));
        }
        asm volatile("cp.async.commit_group;\n");
    }

    for (int t = 0; t < nT; t++) {
        asm volatile("cp.async.wait_group 0;\n");
        __syncthreads();
        if (t + 1 < nT) {
            int k0 = (t + 1) * BK;
            int buf = (t + 1) & 1;
            float* Asn = As + buf * ASZ;
            float* Bsn = Bs + buf * BSZ;
            #pragma unroll
            for (int p = 0; p < 4; p++) {
                int rr = ra + p * 32;
                int gr = row0 + rr, gk = k0 + kq;
                bool ok = (gr < Nrows && gk < K);
                unsigned d = (unsigned)__cvta_generic_to_shared(&Asn[rr * AST + kq]);
                const float* s = ok ? (A + (size_t)gr * K + gk) : A;
                int sz = ok ? 16 : 0;
                asm volatile("cp.async.ca.shared.global [%0], [%1], 16, %2;\n" :: "r"(d), "l"(s), "r"(sz));
            }
            #pragma unroll
            for (int p = 0; p < 4; p++) {
                int kr = kb + p * 8;
                int gk = k0 + kr, gc = col0 + nq;
                bool ok = (gk < K && gc < M);
                unsigned d = (unsigned)__cvta_generic_to_shared(&Bsn[kr * BST + nq]);
                const float* s = ok ? (B + (size_t)gk * M + gc) : B;
                int sz = ok ? 16 : 0;
                asm volatile("cp.async.ca.shared.global [%0], [%1], 16, %2;\n" :: "r"(d), "l"(s), "r"(sz));
            }
            asm volatile("cp.async.commit_group;\n");
        }

        const float* Asb = As + (t & 1) * ASZ;
        const float* Bsb = Bs + (t & 1) * BSZ;
        #pragma unroll
        for (int ks = 0; ks < 4; ks++) {
            int k8 = ks * 8;
            uint32_t af[2][4], bf[8][2];
            int ar = warp_m * 32 + lq;
            int ac = k8 + lr;
            #pragma unroll
            for (int mt = 0; mt < 2; mt++) {
                const float* base = Asb + (ar + mt * 16) * AST + ac;
                af[mt][0] = tf32u(base[0]);
                af[mt][1] = tf32u(base[8 * AST]);
                af[mt][2] = tf32u(base[4]);
                af[mt][3] = tf32u(base[8 * AST + 4]);
            }
            int bc = warp_n * 64 + lq;
            #pragma unroll
            for (int nt = 0; nt < 8; nt++) {
                const float* base = Bsb + (k8 + lr) * BST + bc + nt * 8;
                bf[nt][0] = __float_as_uint(base[0]);
                bf[nt][1] = __float_as_uint(base[4 * BST]);
            }
            #pragma unroll
            for (int mt = 0; mt < 2; mt++)
                #pragma unroll
                for (int nt = 0; nt < 8; nt++)
                    mma_tf32(acc[mt][nt], af[mt], bf[nt]);
        }
        __syncthreads();
    }

    // --- epilogue: pairwise (float2) stores, vector pool reduction ---
    #pragma unroll
    for (int mt = 0; mt < 2; mt++) {
        #pragma unroll
        for (int half = 0; half < 2; half++) {
            int row = row0 + warp_m * 32 + mt * 16 + lq + half * 8;
            if (row >= Nrows) continue;
            int bg = (mode == 1) ? batch[row] : 0;
            #pragma unroll
            for (int nt = 0; nt < 8; nt++) {
                int col = col0 + warp_n * 64 + nt * 8 + lr * 2;
                if (col >= M) continue;
                float v0 = acc[mt][nt][half * 2 + 0] + bias[col];
                float v1 = acc[mt][nt][half * 2 + 1] + bias[col + 1];
                if (mode == 0) {
                    v0 = fmaxf(v0, 0.f); v1 = fmaxf(v1, 0.f);
                } else if (mode != 3) {
                    float sc0 = bng[col] * rsqrtf(bnv[col] + EPS);
                    float sc1 = bng[col + 1] * rsqrtf(bnv[col + 1] + EPS);
                    v0 = (v0 - bnm[col]) * sc0 + bnb[col];
                    v1 = (v1 - bnm[col + 1]) * sc1 + bnb[col + 1];
                    if (mode == 1) { v0 = fmaxf(v0, 0.f); v1 = fmaxf(v1, 0.f); }
                }
                *(float2*)(C + (size_t)row * M + col) = make_float2(v0, v1);
                if (mode == 1) red2(pool + (size_t)bg * DD + col, v0, v1);
            }
        }
    }
}

// ---------------- launch ----------------
extern "C" void kernel_launch(void* const* d_in, const int* in_sizes, int n_in,
                              void* d_out, int out_size) {
    const int*   x_atom  = (const int*)d_in[0];
    const int*   x_chir  = (const int*)d_in[1];
    const int*   src     = (const int*)d_in[2];
    const int*   dst     = (const int*)d_in[3];
    const int*   etype   = (const int*)d_in[4];
    const int*   edir    = (const int*)d_in[5];
    const int*   batch   = (const int*)d_in[6];
    const float* x_emb1  = (const float*)d_in[7];
    const float* x_emb2  = (const float*)d_in[8];
    const float* edge_e1 = (const float*)d_in[9];
    const float* edge_e2 = (const float*)d_in[10];
    const float* mlp_w1  = (const float*)d_in[11];
    const float* mlp_b1  = (const float*)d_in[12];
    const float* mlp_w2  = (const float*)d_in[13];
    const float* mlp_b2  = (const float*)d_in[14];
    const float* bng     = (const float*)d_in[15];
    const float* bnb     = (const float*)d_in[16];
    const float* bnm     = (const float*)d_in[17];
    const float* bnv     = (const float*)d_in[18];
    const float* vn_emb  = (const float*)d_in[19];
    const float* vn_w1   = (const float*)d_in[20];
    const float* vn_b1   = (const float*)d_in[21];
    const float* vn_lng  = (const float*)d_in[22];
    const float* vn_lnb  = (const float*)d_in[23];
    const float* vn_w2   = (const float*)d_in[24];
    const float* vn_b2   = (const float*)d_in[25];
    float* out = (float*)d_out;

    float *p_h, *p_aggr, *p_hid, *p_pool, *p_vn, *p_vnin, *p_vnt, *p_cnt;
    float *p_w1r, *p_w2r, *p_vw1r, *p_vw2r;
    int *p_tc, *p_dc;
    cudaGetSymbolAddress((void**)&p_h, g_h);
    cudaGetSymbolAddress((void**)&p_aggr, g_aggr);
    cudaGetSymbolAddress((void**)&p_hid, g_hid);
    cudaGetSymbolAddress((void**)&p_pool, g_pool);
    cudaGetSymbolAddress((void**)&p_vn, g_vn);
    cudaGetSymbolAddress((void**)&p_vnin, g_vnin);
    cudaGetSymbolAddress((void**)&p_vnt, g_vnt);
    cudaGetSymbolAddress((void**)&p_cnt, g_cnt);
    cudaGetSymbolAddress((void**)&p_w1r, g_w1r);
    cudaGetSymbolAddress((void**)&p_w2r, g_w2r);
    cudaGetSymbolAddress((void**)&p_vw1r, g_vw1r);
    cudaGetSymbolAddress((void**)&p_vw2r, g_vw2r);
    cudaGetSymbolAddress((void**)&p_tc, g_tc);
    cudaGetSymbolAddress((void**)&p_dc, g_dc);

    cudaFuncSetAttribute(k_gemm_tf32, cudaFuncAttributeMaxDynamicSharedMemorySize, SMEM_GEMM);

    const long ND = (long)NN * DD;
    const long GD = (long)GG * DD;
    const int TPB = 256;
    dim3 bElem((unsigned)((ND + TPB - 1) / TPB));
    dim3 bGD((unsigned)((GD + TPB - 1) / TPB));

    {
        long n1 = (long)LL * DD * D2;
        long n2 = (long)LL * D2 * DD;
        long n3 = (long)(LL - 1) * DD * DD;
        k_round<<<(unsigned)((n1 + TPB - 1) / TPB), TPB>>>(mlp_w1, p_w1r, n1);
        k_round<<<(unsigned)((n2 + TPB - 1) / TPB), TPB>>>(mlp_w2, p_w2r, n2);
        k_round<<<(unsigned)((n3 + TPB - 1) / TPB), TPB>>>(vn_w1, p_vw1r, n3);
        k_round<<<(unsigned)((n3 + TPB - 1) / TPB), TPB>>>(vn_w2, p_vw2r, n3);
    }

    k_zero<<<(GG + TPB - 1) / TPB, TPB>>>(p_cnt, GG);
    k_count<<<(NN + TPB - 1) / TPB, TPB>>>(batch, p_cnt, NN);
    k_zeroi<<<(unsigned)(((long)NN * 6 + TPB - 1) / TPB), TPB>>>(p_tc, (long)NN * 6);
    k_zeroi<<<(unsigned)(((long)NN * 3 + TPB - 1) / TPB), TPB>>>(p_dc, (long)NN * 3);
    k_edgehist<<<(EE + TPB - 1) / TPB, TPB>>>(dst, etype, edir, p_tc, p_dc, EE);

    // h = node embeddings only; vn starts at vn_emb and is added at consumption
    k_init_h<<<bElem, TPB>>>(x_atom, x_chir, x_emb1, x_emb2, p_h, ND);
    k_init_vn<<<bGD, TPB>>>(vn_emb, p_vn, GD);

    for (int l = 0; l < LL; l++) {
        const float4* e1l4 = (const float4*)(edge_e1 + (size_t)l * 6 * DD);
        const float4* e2l4 = (const float4*)(edge_e2 + (size_t)l * 3 * DD);

        k_aggr_init<<<(NN + 7) / 8, 256>>>((const float4*)p_h, (const float4*)p_vn, batch,
                                           e1l4, e2l4, p_tc, p_dc, (float4*)p_aggr, NN);
        k_scatter<<<(EE + 3) / 4, 128>>>((const float4*)p_h, (const float4*)p_vn, batch,
                                         src, dst, (float4*)p_aggr, EE);

        if (l < LL - 1) k_zero<<<bGD, TPB>>>(p_pool, GD);

        {
            dim3 grid((D2 + BN - 1) / BN, (NN + BM - 1) / BM);
            k_gemm_tf32<<<grid, 256, SMEM_GEMM>>>(p_aggr, p_w1r + (size_t)l * DD * D2, p_hid,
                                       NN, DD, D2, mlp_b1 + (size_t)l * D2,
                                       nullptr, nullptr, nullptr, nullptr, nullptr, nullptr, 0);
        }
        {
            float* zdst = (l == LL - 1) ? out : p_h;
            int mode = (l == LL - 1) ? 2 : 1;
            dim3 grid((DD + BN - 1) / BN, (NN + BM - 1) / BM);
            k_gemm_tf32<<<grid, 256, SMEM_GEMM>>>(p_hid, p_w2r + (size_t)l * D2 * DD, zdst,
                                       NN, D2, DD, mlp_b2 + (size_t)l * DD,
                                       bng + (size_t)l * DD, bnb + (size_t)l * DD,
                                       bnm + (size_t)l * DD, bnv + (size_t)l * DD,
                                       p_pool, batch, mode);
        }

        if (l < LL - 1) {
            k_vnprep<<<bGD, TPB>>>(p_pool, p_cnt, p_vn, p_vnin, GD);
            {
                dim3 grid((DD + BN - 1) / BN, (GG + BM - 1) / BM);
                k_gemm_tf32<<<grid, 256, SMEM_GEMM>>>(p_vnin, p_vw1r + (size_t)l * DD * DD, p_vnt,
                                           GG, DD, DD, vn_b1 + (size_t)l * DD,
                                           nullptr, nullptr, nullptr, nullptr, nullptr, nullptr, 3);
            }
            k_ln<<<GG, 128>>>(p_vnt, vn_lng + (size_t)l * DD, vn_lnb + (size_t)l * DD);
            {
                dim3 grid((DD + BN - 1) / BN, (GG + BM - 1) / BM);
                k_gemm_tf32<<<grid, 256, SMEM_GEMM>>>(p_vnt, p_vw2r + (size_t)l * DD * DD, p_vn,
                                           GG, DD, DD, vn_b2 + (size_t)l * DD,
                                           nullptr, nullptr, nullptr, nullptr, nullptr, nullptr, 3);
            }
            // no k_addvn: vn[batch] is added by next layer's aggr_init/scatter,
            // and pooling correctly uses z (pre-vn) via the fused epilogue.
        }
    }
}